// round 1
// baseline (speedup 1.0000x reference)
#include <cuda_runtime.h>
#include <cuda_bf16.h>
#include <cstdint>

// Problem shapes (fixed by the dataset)
#define B_DIM   4096
#define IN_DIM  3136
#define FEAT_DIM 6272
#define OUT_DIM 500

// Hidden spike scratch: 4096 x 6272 floats = ~103 MB, static device array
// (allocation-free per harness rules).
__device__ float g_s1[(size_t)B_DIM * FEAT_DIM];

// ---------------------------------------------------------------------------
// Fused GEMM + threshold:
//   C[M,N] = (A[M,K] @ B[N,K]^T >= 1.0f) ? 1.0f : 0.0f
// A row-major [M,K], B row-major [N,K] (torch Linear weight layout).
// Classic 128x128x16 tile, 256 threads, 8x8 per-thread register tile.
// K must be a multiple of 16 and of 4 (3136 and 6272 both qualify).
// N boundary handled (N=500 case).
// ---------------------------------------------------------------------------
#define BM 128
#define BN 128
#define BK 16
#define TM 8
#define TN 8

__global__ __launch_bounds__(256, 2)
void spike_gemm_kernel(const float* __restrict__ A,
                       const float* __restrict__ B,
                       float* __restrict__ C,
                       int M, int N, int K)
{
    __shared__ float As[BK][BM + 4];
    __shared__ float Bs[BK][BN + 4];

    const int tid = threadIdx.x;
    const int tx = tid & 15;        // 0..15 -> column group
    const int ty = tid >> 4;        // 0..15 -> row group

    const int rowBase = blockIdx.y * BM;
    const int colBase = blockIdx.x * BN;

    float acc[TM][TN];
#pragma unroll
    for (int i = 0; i < TM; i++)
#pragma unroll
        for (int j = 0; j < TN; j++)
            acc[i][j] = 0.0f;

    float a_reg[TM], b_reg[TN];

    for (int kt = 0; kt < K; kt += BK) {
        // --- Load A tile (BM x BK) as float4 along K, store transposed ---
        // 128 rows * 4 float4 = 512 slots, 2 per thread.
#pragma unroll
        for (int s = tid; s < (BM * BK) / 4; s += 256) {
            const int m  = s >> 2;            // 0..127
            const int k4 = (s & 3) << 2;      // 0,4,8,12
            float4 v = *reinterpret_cast<const float4*>(
                &A[(size_t)(rowBase + m) * K + kt + k4]);
            As[k4 + 0][m] = v.x;
            As[k4 + 1][m] = v.y;
            As[k4 + 2][m] = v.z;
            As[k4 + 3][m] = v.w;
        }
        // --- Load B tile (BN x BK) as float4 along K, store transposed ---
#pragma unroll
        for (int s = tid; s < (BN * BK) / 4; s += 256) {
            const int n  = s >> 2;
            const int k4 = (s & 3) << 2;
            float4 v = make_float4(0.f, 0.f, 0.f, 0.f);
            if (colBase + n < N) {
                v = *reinterpret_cast<const float4*>(
                    &B[(size_t)(colBase + n) * K + kt + k4]);
            }
            Bs[k4 + 0][n] = v.x;
            Bs[k4 + 1][n] = v.y;
            Bs[k4 + 2][n] = v.z;
            Bs[k4 + 3][n] = v.w;
        }
        __syncthreads();

#pragma unroll
        for (int k = 0; k < BK; k++) {
#pragma unroll
            for (int i = 0; i < TM; i++) a_reg[i] = As[k][ty * TM + i];
#pragma unroll
            for (int j = 0; j < TN; j++) b_reg[j] = Bs[k][tx * TN + j];
#pragma unroll
            for (int i = 0; i < TM; i++)
#pragma unroll
                for (int j = 0; j < TN; j++)
                    acc[i][j] = fmaf(a_reg[i], b_reg[j], acc[i][j]);
        }
        __syncthreads();
    }

    // --- Epilogue: threshold (IF neuron fire, hard reset -> binary spike) ---
#pragma unroll
    for (int i = 0; i < TM; i++) {
        const int row = rowBase + ty * TM + i;
#pragma unroll
        for (int j = 0; j < TN; j++) {
            const int col = colBase + tx * TN + j;
            if (col < N) {
                C[(size_t)row * N + col] = (acc[i][j] >= 1.0f) ? 1.0f : 0.0f;
            }
        }
    }
}

extern "C" void kernel_launch(void* const* d_in, const int* in_sizes, int n_in,
                              void* d_out, int out_size)
{
    const float* x  = (const float*)d_in[0];  // [4096, 3136] binary
    const float* W1 = (const float*)d_in[1];  // [6272, 3136]
    const float* W2 = (const float*)d_in[2];  // [500, 6272]
    float* out = (float*)d_out;               // [4096, 500]

    float* s1;
    cudaGetSymbolAddress((void**)&s1, g_s1);

    // GEMM1: s1 = step(x @ W1^T)   [4096 x 6272]
    {
        dim3 grid(FEAT_DIM / BN, B_DIM / BM);   // 49 x 32
        spike_gemm_kernel<<<grid, 256>>>(x, W1, s1, B_DIM, FEAT_DIM, IN_DIM);
    }
    // GEMM2: out = step(s1 @ W2^T) [4096 x 500]
    {
        dim3 grid((OUT_DIM + BN - 1) / BN, B_DIM / BM);  // 4 x 32
        spike_gemm_kernel<<<grid, 256>>>(s1, W2, out, B_DIM, OUT_DIM, FEAT_DIM);
    }
}

// round 3
// speedup vs baseline: 2.6353x; 2.6353x over previous
#include <cuda_runtime.h>
#include <cuda_bf16.h>
#include <cstdint>
#include <cstddef>

#define B_DIM    4096
#define IN_DIM   3136
#define FEAT_DIM 6272
#define OUT_DIM  500

// ---------------- static device scratch (allocation-free) ----------------
__device__ __nv_bfloat16 g_xb [(size_t)B_DIM * IN_DIM];     // x as bf16 (exact)
__device__ __nv_bfloat16 g_s1b[(size_t)B_DIM * FEAT_DIM];   // hidden spikes bf16 (exact)
__device__ __nv_bfloat16 g_w1l[3ull * FEAT_DIM * IN_DIM];   // W1 limbs hi/mid/lo
__device__ __nv_bfloat16 g_w2l[3ull * OUT_DIM * FEAT_DIM];  // W2 limbs

// ---------------- PTX helpers (baseline sm_80+ features only) ----------------
__device__ __forceinline__ uint32_t smem_u32(const void* p) {
    uint32_t a;
    asm("{ .reg .u64 t; cvta.to.shared.u64 t, %1; cvt.u32.u64 %0, t; }" : "=r"(a) : "l"(p));
    return a;
}
__device__ __forceinline__ void cp_async16(uint32_t dst, const void* src, int src_bytes) {
    asm volatile("cp.async.cg.shared.global [%0], [%1], 16, %2;"
                 :: "r"(dst), "l"(src), "r"(src_bytes) : "memory");
}
__device__ __forceinline__ void cp_commit() {
    asm volatile("cp.async.commit_group;" ::: "memory");
}
template <int N>
__device__ __forceinline__ void cp_wait() {
    asm volatile("cp.async.wait_group %0;" :: "n"(N) : "memory");
}
__device__ __forceinline__ void ldm_x4(uint32_t* r, uint32_t a) {
    asm volatile("ldmatrix.sync.aligned.m8n8.x4.shared.b16 {%0,%1,%2,%3}, [%4];"
                 : "=r"(r[0]), "=r"(r[1]), "=r"(r[2]), "=r"(r[3]) : "r"(a));
}
__device__ __forceinline__ void mma_bf16(float* c, const uint32_t* a, uint32_t b0, uint32_t b1) {
    asm volatile(
        "mma.sync.aligned.m16n8k16.row.col.f32.bf16.bf16.f32 "
        "{%0,%1,%2,%3}, {%4,%5,%6,%7}, {%8,%9}, {%0,%1,%2,%3};"
        : "+f"(c[0]), "+f"(c[1]), "+f"(c[2]), "+f"(c[3])
        : "r"(a[0]), "r"(a[1]), "r"(a[2]), "r"(a[3]), "r"(b0), "r"(b1));
}

// ---------------- converter kernels ----------------
__global__ void conv_bf16_kernel(const float4* __restrict__ in,
                                 __nv_bfloat162* __restrict__ out, int n4) {
    int i = blockIdx.x * blockDim.x + threadIdx.x;
    if (i < n4) {
        float4 v = in[i];
        out[i * 2 + 0] = __nv_bfloat162(__float2bfloat16_rn(v.x), __float2bfloat16_rn(v.y));
        out[i * 2 + 1] = __nv_bfloat162(__float2bfloat16_rn(v.z), __float2bfloat16_rn(v.w));
    }
}

// exact 3-limb split: w == hi + mid + lo (each residual exact in fp32)
__global__ void split3_kernel(const float4* __restrict__ in,
                              __nv_bfloat16* __restrict__ limbs, size_t n, int n4) {
    int i = blockIdx.x * blockDim.x + threadIdx.x;
    if (i >= n4) return;
    float4 v = in[i];
    float w[4] = {v.x, v.y, v.z, v.w};
    __nv_bfloat16 hi[4], mi[4], lo[4];
#pragma unroll
    for (int j = 0; j < 4; j++) {
        float f = w[j];
        hi[j] = __float2bfloat16_rn(f);
        float r1 = f - __bfloat162float(hi[j]);
        mi[j] = __float2bfloat16_rn(r1);
        float r2 = r1 - __bfloat162float(mi[j]);
        lo[j] = __float2bfloat16_rn(r2);
    }
    __nv_bfloat162* o0 = reinterpret_cast<__nv_bfloat162*>(limbs);
    __nv_bfloat162* o1 = reinterpret_cast<__nv_bfloat162*>(limbs + n);
    __nv_bfloat162* o2 = reinterpret_cast<__nv_bfloat162*>(limbs + 2 * n);
    o0[i * 2 + 0] = __nv_bfloat162(hi[0], hi[1]); o0[i * 2 + 1] = __nv_bfloat162(hi[2], hi[3]);
    o1[i * 2 + 0] = __nv_bfloat162(mi[0], mi[1]); o1[i * 2 + 1] = __nv_bfloat162(mi[2], mi[3]);
    o2[i * 2 + 0] = __nv_bfloat162(lo[0], lo[1]); o2[i * 2 + 1] = __nv_bfloat162(lo[2], lo[3]);
}

// ---------------- fused mma.sync spike GEMM ----------------
//  C[M,Nout] = step( A[M,K] @ W[Nout,K]^T ),  W given as 3 bf16 limbs.
//  Tile 128x128, BK=32, 3 limbs folded into k-loop (same accumulators).
//  256 threads = 8 warps (4 m x 2 n), warp tile 32x64.
//  Smem per stage: A[128][32] + 3 x B[128][32] bf16, 64B rows, xor-swizzled.
#define STAGES 3
#define STAGE_BYTES (4 * 128 * 64)      // 32 KB

template <bool OUT_BF16>
__global__ __launch_bounds__(256, 2)
void spike_mma_gemm(const __nv_bfloat16* __restrict__ A,
                    const __nv_bfloat16* __restrict__ Wl, size_t limbStride,
                    void* __restrict__ Cout, int K, int Nout)
{
    extern __shared__ char smem[];
    const int tid  = threadIdx.x;
    const int lane = tid & 31;
    const int wid  = tid >> 5;
    const int wm   = wid & 3;       // warp row 0..3 (32 rows each)
    const int wn   = wid >> 2;      // warp col 0..1 (64 cols each)
    const int rowBase = blockIdx.x * 128;   // M-fast grid for L2 reuse of W slab
    const int colBase = blockIdx.y * 128;

    const int rL  = lane & 15;      // ldmatrix address row within 16
    const int ccL = lane >> 4;      // ldmatrix 16B-chunk selector (0/1)

    float acc[2][8][4];
#pragma unroll
    for (int i = 0; i < 2; i++)
#pragma unroll
        for (int j = 0; j < 8; j++)
#pragma unroll
            for (int k = 0; k < 4; k++) acc[i][j][k] = 0.0f;

    const uint32_t smem_base = smem_u32(smem);
    const int ITERS = K / 32;

    // ---- async stage loader: A (512 x 16B) + 3 limb B tiles (1536 x 16B) ----
    auto load_stage = [&](int it) {
        const int s  = it % STAGES;
        const int kt = it * 32;
        const uint32_t stA = smem_base + s * STAGE_BYTES;
        const uint32_t stB = stA + 128 * 64;
#pragma unroll
        for (int i = 0; i < 2; i++) {
            const int idx = tid * 2 + i;            // 0..511
            const int r = idx >> 2, c = idx & 3;
            const uint32_t d = stA + r * 64 + (((c ^ (r & 3)) << 4));
            cp_async16(d, A + (size_t)(rowBase + r) * K + kt + c * 8, 16);
        }
#pragma unroll
        for (int j = 0; j < 6; j++) {
            const int idx = tid + j * 256;          // 0..1535
            const int limb = idx >> 9, rem = idx & 511;
            const int r = rem >> 2, c = rem & 3;
            const int gn = colBase + r;
            const int ok = (gn < Nout);
            const int gns = ok ? gn : (Nout - 1);   // safe address, zero-fill when !ok
            const uint32_t d = stB + limb * 8192 + r * 64 + (((c ^ (r & 3)) << 4));
            cp_async16(d, Wl + (size_t)limb * limbStride + (size_t)gns * K + kt + c * 8,
                       ok ? 16 : 0);
        }
        cp_commit();
    };

    load_stage(0);
    if (ITERS > 1) load_stage(1);

    for (int it = 0; it < ITERS; ++it) {
        cp_wait<1>();
        __syncthreads();
        if (it + 2 < ITERS) load_stage(it + 2);

        const int s = it % STAGES;
        const uint32_t stA = smem_base + s * STAGE_BYTES;
        const uint32_t stB = stA + 128 * 64;

#pragma unroll
        for (int ks = 0; ks < 2; ks++) {
            uint32_t afr[2][4];
#pragma unroll
            for (int mt = 0; mt < 2; mt++) {
                const int row = wm * 32 + mt * 16 + rL;
                const uint32_t ad = stA + row * 64 + (((ccL + 2 * ks) ^ (row & 3)) << 4);
                ldm_x4(afr[mt], ad);
            }
#pragma unroll
            for (int limb = 0; limb < 3; limb++) {
                uint32_t bfr[4][4];
#pragma unroll
                for (int nb = 0; nb < 4; nb++) {
                    const int row = wn * 64 + nb * 16 + rL;
                    const uint32_t bd = stB + limb * 8192 + row * 64 +
                                        (((ccL + 2 * ks) ^ (row & 3)) << 4);
                    ldm_x4(bfr[nb], bd);
                }
#pragma unroll
                for (int mt = 0; mt < 2; mt++)
#pragma unroll
                    for (int nb = 0; nb < 4; nb++) {
                        mma_bf16(acc[mt][nb * 2 + 0], afr[mt], bfr[nb][0], bfr[nb][2]);
                        mma_bf16(acc[mt][nb * 2 + 1], afr[mt], bfr[nb][1], bfr[nb][3]);
                    }
            }
        }
    }

    // ---- epilogue: threshold + direct stores ----
    const int g = lane >> 2;        // 0..7
    const int t = lane & 3;         // 0..3
#pragma unroll
    for (int mt = 0; mt < 2; mt++) {
#pragma unroll
        for (int nt = 0; nt < 8; nt++) {
            const float* c = acc[mt][nt];
            const int row = rowBase + wm * 32 + mt * 16 + g;
            const int col = colBase + wn * 64 + nt * 8 + 2 * t;
            if (OUT_BF16) {
                __nv_bfloat16* o = (__nv_bfloat16*)Cout;
                __nv_bfloat162 v0(__float2bfloat16(c[0] >= 1.0f ? 1.0f : 0.0f),
                                  __float2bfloat16(c[1] >= 1.0f ? 1.0f : 0.0f));
                __nv_bfloat162 v1(__float2bfloat16(c[2] >= 1.0f ? 1.0f : 0.0f),
                                  __float2bfloat16(c[3] >= 1.0f ? 1.0f : 0.0f));
                *reinterpret_cast<__nv_bfloat162*>(o + (size_t)row * Nout + col) = v0;
                *reinterpret_cast<__nv_bfloat162*>(o + (size_t)(row + 8) * Nout + col) = v1;
            } else {
                float* o = (float*)Cout;
                if (col < Nout) {   // Nout even, col even -> pair fits
                    float2 v0 = make_float2(c[0] >= 1.0f ? 1.0f : 0.0f,
                                            c[1] >= 1.0f ? 1.0f : 0.0f);
                    float2 v1 = make_float2(c[2] >= 1.0f ? 1.0f : 0.0f,
                                            c[3] >= 1.0f ? 1.0f : 0.0f);
                    *reinterpret_cast<float2*>(o + (size_t)row * Nout + col) = v0;
                    *reinterpret_cast<float2*>(o + (size_t)(row + 8) * Nout + col) = v1;
                }
            }
        }
    }
}

// ---------------- host launcher ----------------
extern "C" void kernel_launch(void* const* d_in, const int* in_sizes, int n_in,
                              void* d_out, int out_size)
{
    const float* x  = (const float*)d_in[0];  // [4096, 3136] binary
    const float* W1 = (const float*)d_in[1];  // [6272, 3136]
    const float* W2 = (const float*)d_in[2];  // [500, 6272]
    float* out = (float*)d_out;               // [4096, 500]

    __nv_bfloat16 *xb, *s1b, *w1l, *w2l;
    cudaGetSymbolAddress((void**)&xb,  g_xb);
    cudaGetSymbolAddress((void**)&s1b, g_s1b);
    cudaGetSymbolAddress((void**)&w1l, g_w1l);
    cudaGetSymbolAddress((void**)&w2l, g_w2l);

    // converters
    {
        int n4 = (B_DIM * IN_DIM) / 4;
        conv_bf16_kernel<<<(n4 + 255) / 256, 256>>>(
            (const float4*)x, (__nv_bfloat162*)xb, n4);
    }
    {
        size_t n = (size_t)FEAT_DIM * IN_DIM;
        int n4 = (int)(n / 4);
        split3_kernel<<<(n4 + 255) / 256, 256>>>((const float4*)W1, w1l, n, n4);
    }
    {
        size_t n = (size_t)OUT_DIM * FEAT_DIM;
        int n4 = (int)(n / 4);
        split3_kernel<<<(n4 + 255) / 256, 256>>>((const float4*)W2, w2l, n, n4);
    }

    constexpr int SMEM = STAGES * STAGE_BYTES;   // 96 KB

    // GEMM1: s1 = step(x @ W1^T)  [4096 x 6272]
    {
        cudaFuncSetAttribute(spike_mma_gemm<true>,
                             cudaFuncAttributeMaxDynamicSharedMemorySize, SMEM);
        dim3 grid(B_DIM / 128, FEAT_DIM / 128);          // (32, 49) M-fast
        spike_mma_gemm<true><<<grid, 256, SMEM>>>(
            xb, w1l, (size_t)FEAT_DIM * IN_DIM, (void*)s1b, IN_DIM, FEAT_DIM);
    }
    // GEMM2: out = step(s1 @ W2^T)  [4096 x 500]
    {
        cudaFuncSetAttribute(spike_mma_gemm<false>,
                             cudaFuncAttributeMaxDynamicSharedMemorySize, SMEM);
        dim3 grid(B_DIM / 128, (OUT_DIM + 127) / 128);   // (32, 4)
        spike_mma_gemm<false><<<grid, 256, SMEM>>>(
            s1b, w2l, (size_t)OUT_DIM * FEAT_DIM, (void*)out, FEAT_DIM, OUT_DIM);
    }
}